// round 4
// baseline (speedup 1.0000x reference)
#include <cuda_runtime.h>
#include <math.h>

#define BB   512
#define LL   256
#define HH   512
#define AD   128
#define CD   512
#define G4H  2048      // 4*H
#define KP   512       // per-pair K (all GEMM pairs have K=512)
#define BH   (BB*HH)   // 262144

// ---------------- device scratch (no allocations allowed) ----------------
__device__ float g_gates[BB * G4H];     // 4 MB
__device__ float g_vbias[G4H];
__device__ float g_atth[BB * AD];
__device__ float g_scores[BB * LL];
__device__ float g_weight[BB * LL];
__device__ float g_attres[BB * CD];

__device__ __forceinline__ float sigf(float x) { return 1.0f / (1.0f + expf(-x)); }

// ---------------- layer-0 bias: b_ih0 + b_hh0 + video @ w_ih0[:,512:1024].T
__global__ void k_vbias(const float* __restrict__ video,
                        const float* __restrict__ w_ih0,
                        const float* __restrict__ b_ih0,
                        const float* __restrict__ b_hh0) {
    int n = blockIdx.x * blockDim.x + threadIdx.x;
    if (n >= G4H) return;
    const float* w = w_ih0 + (size_t)n * 1536 + 512;
    float acc = b_ih0[n] + b_hh0[n];
    #pragma unroll 8
    for (int k = 0; k < 512; k++) acc += video[k] * w[k];
    g_vbias[n] = acc;
}

// ---------------- generic 3-pair NT GEMM into g_gates:
// g_gates[512,2048] = sum_p A_p @ W_p^T + bias
// Tile 64x64, BK=16, 256 threads, 4x4 microtile.
// a0_mode: 0 -> use A0 arg; 1 -> A0 = g_attres (device scratch)
// bias_mode: 0 -> bias = bias0 + bias1 args; 1 -> bias = g_vbias
__global__ __launch_bounds__(256)
void k_gemm3(const float* __restrict__ A0, int lda0, const float* __restrict__ W0, int ldw0,
             const float* __restrict__ A1, int lda1, const float* __restrict__ W1, int ldw1,
             const float* __restrict__ A2, int lda2, const float* __restrict__ W2, int ldw2,
             const float* __restrict__ bias0, const float* __restrict__ bias1,
             int a0_mode, int bias_mode) {
    __shared__ float As[16][64];
    __shared__ float Ws[16][64];
    int tid = threadIdx.x;
    int m0 = blockIdx.y * 64;
    int n0 = blockIdx.x * 64;
    int ty = tid / 16, tx = tid % 16;
    int lr = tid >> 2;            // 0..63 tile row
    int lc = (tid & 3) * 4;       // k sub-offset 0,4,8,12
    float acc[4][4] = {};

    const float* Aps[3] = {(a0_mode ? (const float*)g_attres : A0), A1, A2};
    const float* Wps[3] = {W0, W1, W2};
    int ldas[3] = {lda0, lda1, lda2};
    int ldws[3] = {ldw0, ldw1, ldw2};

    #pragma unroll
    for (int p = 0; p < 3; p++) {
        const float* Ap = Aps[p];
        const float* Wp = Wps[p];
        size_t lda = (size_t)ldas[p], ldw = (size_t)ldws[p];
        for (int k0 = 0; k0 < KP; k0 += 16) {
            float4 av = *reinterpret_cast<const float4*>(Ap + (size_t)(m0 + lr) * lda + k0 + lc);
            float4 wv = *reinterpret_cast<const float4*>(Wp + (size_t)(n0 + lr) * ldw + k0 + lc);
            __syncthreads();
            As[lc + 0][lr] = av.x; As[lc + 1][lr] = av.y; As[lc + 2][lr] = av.z; As[lc + 3][lr] = av.w;
            Ws[lc + 0][lr] = wv.x; Ws[lc + 1][lr] = wv.y; Ws[lc + 2][lr] = wv.z; Ws[lc + 3][lr] = wv.w;
            __syncthreads();
            #pragma unroll
            for (int kk = 0; kk < 16; kk++) {
                float4 a4 = *reinterpret_cast<const float4*>(&As[kk][ty * 4]);
                float4 b4 = *reinterpret_cast<const float4*>(&Ws[kk][tx * 4]);
                float a[4] = {a4.x, a4.y, a4.z, a4.w};
                float b[4] = {b4.x, b4.y, b4.z, b4.w};
                #pragma unroll
                for (int i = 0; i < 4; i++)
                    #pragma unroll
                    for (int j = 0; j < 4; j++)
                        acc[i][j] += a[i] * b[j];
            }
        }
    }
    #pragma unroll
    for (int i = 0; i < 4; i++) {
        int m = m0 + ty * 4 + i;
        #pragma unroll
        for (int j = 0; j < 4; j++) {
            int n = n0 + tx * 4 + j;
            float v = acc[i][j];
            if (bias_mode) {
                v += g_vbias[n];
            } else {
                v += bias0[n] + bias1[n];
            }
            g_gates[(size_t)m * G4H + n] = v;
        }
    }
}

// ---------------- LSTM activation: g_gates -> (h, c)
__global__ void k_lstm_act(const float* __restrict__ cprev,
                           float* __restrict__ hout, float* __restrict__ cout,
                           float* __restrict__ hout2) {
    int idx = blockIdx.x * blockDim.x + threadIdx.x;
    if (idx >= BH) return;
    int b = idx / HH, j = idx % HH;
    const float* g = g_gates + (size_t)b * G4H;
    float gi = g[j], gf = g[HH + j], gg = g[2 * HH + j], go = g[3 * HH + j];
    float c = sigf(gf) * cprev[idx] + sigf(gi) * tanhf(gg);
    float h = sigf(go) * tanhf(c);
    hout[idx] = h;
    cout[idx] = c;
    if (hout2) hout2[idx] = h;
}

// ---------------- att_h = h1 @ wh.T + bh  ([B,128])
__global__ void k_atth(const float* __restrict__ h1, const float* __restrict__ wh,
                       const float* __restrict__ bh) {
    __shared__ float hs[512];
    int b = blockIdx.x, t = threadIdx.x;   // 128 threads
    for (int i = t; i < 512; i += 128) hs[i] = h1[(size_t)b * 512 + i];
    __syncthreads();
    const float* w = wh + (size_t)t * 512;
    float acc = bh[t];
    #pragma unroll 8
    for (int k = 0; k < 512; k++) acc += hs[k] * w[k];
    g_atth[b * AD + t] = acc;
}

// ---------------- fused attention scores:
// S[m,a] = clip2d[m,:] . wc[a,:] ; scores[m] = sum_a tanh(S+bc+atth[b]) * wa[a] + ba
// block = 128 rows x 128 cols (full A), 256 threads, 8x8 microtile, BK=8.
__global__ __launch_bounds__(256)
void k_att_scores(const float* __restrict__ clip, const float* __restrict__ wc,
                  const float* __restrict__ bc, const float* __restrict__ wa,
                  const float* __restrict__ ba) {
    __shared__ float As[8][128];
    __shared__ float Ws[8][128];
    __shared__ float red[128 * 17];
    int tid = threadIdx.x;
    int m0 = blockIdx.x * 128;           // row within [B*L]
    int bidx = m0 >> 8;                  // batch index (L=256, blocks are b-aligned)
    int ty = tid / 16, tx = tid % 16;
    int lr = tid >> 1;                   // 0..127
    int lc = (tid & 1) * 4;              // 0 or 4
    float acc[8][8] = {};
    const float* Abase = clip + (size_t)m0 * CD;

    for (int k0 = 0; k0 < CD; k0 += 8) {
        float4 av = *reinterpret_cast<const float4*>(Abase + (size_t)lr * CD + k0 + lc);
        float4 wv = *reinterpret_cast<const float4*>(wc + (size_t)lr * CD + k0 + lc);
        __syncthreads();
        As[lc + 0][lr] = av.x; As[lc + 1][lr] = av.y; As[lc + 2][lr] = av.z; As[lc + 3][lr] = av.w;
        Ws[lc + 0][lr] = wv.x; Ws[lc + 1][lr] = wv.y; Ws[lc + 2][lr] = wv.z; Ws[lc + 3][lr] = wv.w;
        __syncthreads();
        #pragma unroll
        for (int kk = 0; kk < 8; kk++) {
            float4 t0 = *reinterpret_cast<const float4*>(&As[kk][ty * 8]);
            float4 t1 = *reinterpret_cast<const float4*>(&As[kk][ty * 8 + 4]);
            float4 u0 = *reinterpret_cast<const float4*>(&Ws[kk][tx * 8]);
            float4 u1 = *reinterpret_cast<const float4*>(&Ws[kk][tx * 8 + 4]);
            float a[8] = {t0.x, t0.y, t0.z, t0.w, t1.x, t1.y, t1.z, t1.w};
            float b[8] = {u0.x, u0.y, u0.z, u0.w, u1.x, u1.y, u1.z, u1.w};
            #pragma unroll
            for (int i = 0; i < 8; i++)
                #pragma unroll
                for (int j = 0; j < 8; j++)
                    acc[i][j] += a[i] * b[j];
        }
    }

    // epilogue: tanh + dot with wa, reduce across the 16 thread-columns
    const float* atthp = g_atth + bidx * AD;
    float part[8];
    #pragma unroll
    for (int i = 0; i < 8; i++) part[i] = 0.0f;
    #pragma unroll
    for (int j = 0; j < 8; j++) {
        int col = tx * 8 + j;
        float add = bc[col] + atthp[col];
        float wav = wa[col];
        #pragma unroll
        for (int i = 0; i < 8; i++) {
            float v = tanhf(acc[i][j] + add);
            part[i] += v * wav;
        }
    }
    #pragma unroll
    for (int i = 0; i < 8; i++) red[(ty * 8 + i) * 17 + tx] = part[i];
    __syncthreads();
    if (tid < 128) {
        float s = 0.0f;
        #pragma unroll
        for (int t2 = 0; t2 < 16; t2++) s += red[tid * 17 + t2];
        g_scores[m0 + tid] = s + ba[0];
    }
}

// ---------------- masked softmax + renorm (per batch row, L=256)
__global__ void k_softmax(const int* __restrict__ mask) {
    __shared__ float sh[256];
    int b = blockIdx.x, t = threadIdx.x;
    float s = g_scores[b * LL + t];
    sh[t] = s;
    __syncthreads();
    for (int o = 128; o > 0; o >>= 1) {
        if (t < o) sh[t] = fmaxf(sh[t], sh[t + o]);
        __syncthreads();
    }
    float mx = sh[0];
    __syncthreads();
    float p = expf(s - mx);
    float pm = p * (float)mask[b * LL + t];
    sh[t] = pm;
    __syncthreads();
    for (int o = 128; o > 0; o >>= 1) {
        if (t < o) sh[t] += sh[t + o];
        __syncthreads();
    }
    float denom = sh[0];
    g_weight[b * LL + t] = pm / denom;
}

// ---------------- att_res[b,c] = sum_l weight[b,l]*clip[b,l,c]
__global__ void k_attres(const float* __restrict__ clip) {
    __shared__ float w[256];
    int b = blockIdx.x, t = threadIdx.x;   // 256 threads
    w[t] = g_weight[b * LL + t];
    __syncthreads();
    const float* cb = clip + (size_t)b * LL * CD;
    float a0 = 0.0f, a1 = 0.0f;
    for (int l = 0; l < LL; l++) {
        float wl = w[l];
        a0 += wl * cb[(size_t)l * CD + t];
        a1 += wl * cb[(size_t)l * CD + t + 256];
    }
    g_attres[b * CD + t] = a0;
    g_attres[b * CD + t + 256] = a1;
}

// ---------------- launch ----------------
extern "C" void kernel_launch(void* const* d_in, const int* in_sizes, int n_in,
                              void* d_out, int out_size) {
    const float* xt      = (const float*)d_in[0];
    const float* video   = (const float*)d_in[1];
    const float* event   = (const float*)d_in[2];
    const float* clip    = (const float*)d_in[3];
    const int*   cmask   = (const int*)d_in[4];
    const float* state_h = (const float*)d_in[5];
    const float* state_c = (const float*)d_in[6];
    const float* w_ih0   = (const float*)d_in[7];
    const float* w_hh0   = (const float*)d_in[8];
    const float* b_ih0   = (const float*)d_in[9];
    const float* b_hh0   = (const float*)d_in[10];
    const float* w_ih1   = (const float*)d_in[11];
    const float* w_hh1   = (const float*)d_in[12];
    const float* b_ih1   = (const float*)d_in[13];
    const float* b_hh1   = (const float*)d_in[14];
    const float* w_ih2   = (const float*)d_in[15];
    const float* w_hh2   = (const float*)d_in[16];
    const float* b_ih2   = (const float*)d_in[17];
    const float* b_hh2   = (const float*)d_in[18];
    const float* wc      = (const float*)d_in[19];
    const float* bc      = (const float*)d_in[20];
    const float* wh      = (const float*)d_in[21];
    const float* bh      = (const float*)d_in[22];
    const float* wa      = (const float*)d_in[23];
    const float* ba      = (const float*)d_in[24];

    float* out = (float*)d_out;
    float* h2o = out;            // h2: [B,H]
    float* nh  = out + BH;       // new_h: 3 x [B,H]
    float* nc  = out + 4 * BH;   // new_c: 3 x [B,H]

    dim3 ggrid(G4H / 64, BB / 64);   // (32, 8)

    // layer 0 bias (folds in the batch-invariant video @ w_ih0[:,512:1024] term)
    k_vbias<<<G4H / 256, 256>>>(video, w_ih0, b_ih0, b_hh0);

    // layer 0: gates = xt@Wih0[:,:512]^T + pre_h@Wih0[:,1024:]^T + h0_prev@Whh0^T + vbias
    k_gemm3<<<ggrid, 256>>>(
        xt, 512,               w_ih0, 1536,
        state_h + 2 * BH, 512, w_ih0 + 1024, 1536,
        state_h, 512,          w_hh0, 512,
        b_ih0, b_hh0, /*a0_mode=*/0, /*bias_mode=*/1);
    k_lstm_act<<<BH / 256, 256>>>(state_c, nh, nc, nullptr);

    // layer 1: gates = event@Wih1[:,:512]^T + h0@Wih1[:,512:]^T + h1_prev@Whh1^T + b
    k_gemm3<<<ggrid, 256>>>(
        event, 512,            w_ih1, 1024,
        nh, 512,               w_ih1 + 512, 1024,
        state_h + BH, 512,     w_hh1, 512,
        b_ih1, b_hh1, 0, 0);
    k_lstm_act<<<BH / 256, 256>>>(state_c + BH, nh + BH, nc + BH, nullptr);

    // attention
    k_atth<<<BB, 128>>>(nh + BH, wh, bh);
    k_att_scores<<<(BB * LL) / 128, 256>>>(clip, wc, bc, wa, ba);
    k_softmax<<<BB, 256>>>(cmask);
    k_attres<<<BB, 256>>>(clip);

    // layer 2: gates = att_res@Wih2[:,:512]^T + h1@Wih2[:,512:]^T + h2_prev@Whh2^T + b
    k_gemm3<<<ggrid, 256>>>(
        nullptr, 512,          w_ih2, 1024,
        nh + BH, 512,          w_ih2 + 512, 1024,
        state_h + 2 * BH, 512, w_hh2, 512,
        b_ih2, b_hh2, /*a0_mode=*/1, 0);
    k_lstm_act<<<BH / 256, 256>>>(state_c + 2 * BH, nh + 2 * BH, nc + 2 * BH, h2o);
}

// round 5
// speedup vs baseline: 1.8836x; 1.8836x over previous
#include <cuda_runtime.h>
#include <math.h>
#include <stdint.h>

#define BB   512
#define LL   256
#define HH   512
#define AD   128
#define CD   512
#define G4H  2048      // 4*H
#define BH   (BB*HH)   // 262144

// ---------------- device scratch ----------------
__device__ alignas(16) float g_gates[BB * G4H];     // 4 MB
__device__ alignas(16) float g_vbias[G4H];
__device__ alignas(16) float g_atth[BB * AD];
__device__ alignas(16) float g_scores[BB * LL];
__device__ alignas(16) float g_weight[BB * LL];
__device__ alignas(16) float g_attres[BB * CD];

__device__ __forceinline__ float sigf(float x) { return 1.0f / (1.0f + expf(-x)); }

__device__ __forceinline__ uint32_t f2tf(float f) {
    uint32_t u;
    asm("cvt.rna.tf32.f32 %0, %1;" : "=r"(u) : "f"(f));
    return u;
}

__device__ __forceinline__ float tanh_ap(float x) {
    float y;
    asm("tanh.approx.f32 %0, %1;" : "=f"(y) : "f"(x));
    return y;
}

// D += A*B, m16n8k8 tf32, A row-major frag (4 regs), B col-major frag (2 regs)
__device__ __forceinline__ void mma8(float* c, const uint32_t* a, const uint32_t* b) {
    asm volatile("mma.sync.aligned.m16n8k8.row.col.f32.tf32.tf32.f32 "
        "{%0,%1,%2,%3}, {%4,%5,%6,%7}, {%8,%9}, {%0,%1,%2,%3};"
        : "+f"(c[0]), "+f"(c[1]), "+f"(c[2]), "+f"(c[3])
        : "r"(a[0]), "r"(a[1]), "r"(a[2]), "r"(a[3]), "r"(b[0]), "r"(b[1]));
}

// ---------------- layer-0 bias: b_ih0 + b_hh0 + video @ w_ih0[:,512:1024].T
__global__ void k_vbias(const float* __restrict__ video,
                        const float* __restrict__ w_ih0,
                        const float* __restrict__ b_ih0,
                        const float* __restrict__ b_hh0) {
    int n = blockIdx.x * blockDim.x + threadIdx.x;
    if (n >= G4H) return;
    const float* w = w_ih0 + (size_t)n * 1536 + 512;
    float acc = b_ih0[n] + b_hh0[n];
    #pragma unroll 8
    for (int k = 0; k < 512; k++) acc += video[k] * w[k];
    g_vbias[n] = acc;
}

// ================= tf32 tensor-core 3-pair NT GEMM =================
// g_gates[512,2048] = sum_p A_p[512,512] @ W_p[2048,512]^T + bias
// Block tile 64x64, BK=16, 128 threads (4 warps 2x2, warp tile 32x32).
// Double-buffered smem, tf32 converted at load.

// one K=512 pair, accumulating into acc
__device__ __forceinline__ void gemm_pair64(
    const float* __restrict__ Ap, int lda,
    const float* __restrict__ Wp, int ldw,
    int m0, int n0, int tid, int lane, int wm, int wn,
    uint32_t* As0, uint32_t* As1, uint32_t* Bs0, uint32_t* Bs1,
    float acc[2][4][4])
{
    int lrow = tid >> 2;               // 0..31
    int kc   = (tid & 3) * 4;          // 0,4,8,12
    const float* a0p = Ap + (size_t)(m0 + lrow) * lda + kc;
    const float* a1p = Ap + (size_t)(m0 + lrow + 32) * lda + kc;
    const float* b0p = Wp + (size_t)(n0 + lrow) * ldw + kc;
    const float* b1p = Wp + (size_t)(n0 + lrow + 32) * ldw + kc;
    int s0 = lrow * 20 + kc;
    int s1 = (lrow + 32) * 20 + kc;

    uint32_t* As = As0; uint32_t* Asn = As1;
    uint32_t* Bs = Bs0; uint32_t* Bsn = Bs1;

    // prologue k0=0
    {
        float4 ra0 = *reinterpret_cast<const float4*>(a0p);
        float4 ra1 = *reinterpret_cast<const float4*>(a1p);
        float4 rb0 = *reinterpret_cast<const float4*>(b0p);
        float4 rb1 = *reinterpret_cast<const float4*>(b1p);
        As[s0]=f2tf(ra0.x); As[s0+1]=f2tf(ra0.y); As[s0+2]=f2tf(ra0.z); As[s0+3]=f2tf(ra0.w);
        As[s1]=f2tf(ra1.x); As[s1+1]=f2tf(ra1.y); As[s1+2]=f2tf(ra1.z); As[s1+3]=f2tf(ra1.w);
        Bs[s0]=f2tf(rb0.x); Bs[s0+1]=f2tf(rb0.y); Bs[s0+2]=f2tf(rb0.z); Bs[s0+3]=f2tf(rb0.w);
        Bs[s1]=f2tf(rb1.x); Bs[s1+1]=f2tf(rb1.y); Bs[s1+2]=f2tf(rb1.z); Bs[s1+3]=f2tf(rb1.w);
    }
    __syncthreads();

    for (int s = 0; s < 32; s++) {
        float4 ra0, ra1, rb0, rb1;
        if (s < 31) {
            int k0 = (s + 1) * 16;
            ra0 = *reinterpret_cast<const float4*>(a0p + k0);
            ra1 = *reinterpret_cast<const float4*>(a1p + k0);
            rb0 = *reinterpret_cast<const float4*>(b0p + k0);
            rb1 = *reinterpret_cast<const float4*>(b1p + k0);
        }
        // compute from As/Bs
        #pragma unroll
        for (int kk = 0; kk < 16; kk += 8) {
            uint32_t af[2][4], bf[4][2];
            int ar = wm + (lane >> 2);
            int ac = kk + (lane & 3);
            #pragma unroll
            for (int mt = 0; mt < 2; mt++) {
                int r = ar + mt * 16;
                af[mt][0] = As[r * 20 + ac];
                af[mt][1] = As[(r + 8) * 20 + ac];
                af[mt][2] = As[r * 20 + ac + 4];
                af[mt][3] = As[(r + 8) * 20 + ac + 4];
            }
            #pragma unroll
            for (int nt = 0; nt < 4; nt++) {
                int c = wn + nt * 8 + (lane >> 2);
                bf[nt][0] = Bs[c * 20 + ac];
                bf[nt][1] = Bs[c * 20 + ac + 4];
            }
            #pragma unroll
            for (int mt = 0; mt < 2; mt++)
                #pragma unroll
                for (int nt = 0; nt < 4; nt++)
                    mma8(acc[mt][nt], af[mt], bf[nt]);
        }
        if (s < 31) {
            Asn[s0]=f2tf(ra0.x); Asn[s0+1]=f2tf(ra0.y); Asn[s0+2]=f2tf(ra0.z); Asn[s0+3]=f2tf(ra0.w);
            Asn[s1]=f2tf(ra1.x); Asn[s1+1]=f2tf(ra1.y); Asn[s1+2]=f2tf(ra1.z); Asn[s1+3]=f2tf(ra1.w);
            Bsn[s0]=f2tf(rb0.x); Bsn[s0+1]=f2tf(rb0.y); Bsn[s0+2]=f2tf(rb0.z); Bsn[s0+3]=f2tf(rb0.w);
            Bsn[s1]=f2tf(rb1.x); Bsn[s1+1]=f2tf(rb1.y); Bsn[s1+2]=f2tf(rb1.z); Bsn[s1+3]=f2tf(rb1.w);
        }
        __syncthreads();
        uint32_t* t;
        t = As; As = Asn; Asn = t;
        t = Bs; Bs = Bsn; Bsn = t;
    }
}

__global__ __launch_bounds__(128)
void k_gemm3_tf32(const float* __restrict__ A0, int lda0, const float* __restrict__ W0, int ldw0,
                  const float* __restrict__ A1, int lda1, const float* __restrict__ W1, int ldw1,
                  const float* __restrict__ A2, int lda2, const float* __restrict__ W2, int ldw2,
                  const float* __restrict__ bias0, const float* __restrict__ bias1,
                  int a0_mode, int bias_mode)
{
    __shared__ uint32_t As0[64 * 20], As1[64 * 20];
    __shared__ uint32_t Bs0[64 * 20], Bs1[64 * 20];
    int tid = threadIdx.x;
    int wid = tid >> 5, lane = tid & 31;
    int m0 = blockIdx.y * 64, n0 = blockIdx.x * 64;
    int wm = (wid >> 1) * 32, wn = (wid & 1) * 32;

    if (a0_mode) A0 = g_attres;

    float acc[2][4][4];
    #pragma unroll
    for (int i = 0; i < 2; i++)
        #pragma unroll
        for (int j = 0; j < 4; j++)
            #pragma unroll
            for (int k = 0; k < 4; k++) acc[i][j][k] = 0.0f;

    gemm_pair64(A0, lda0, W0, ldw0, m0, n0, tid, lane, wm, wn, As0, As1, Bs0, Bs1, acc);
    gemm_pair64(A1, lda1, W1, ldw1, m0, n0, tid, lane, wm, wn, As0, As1, Bs0, Bs1, acc);
    gemm_pair64(A2, lda2, W2, ldw2, m0, n0, tid, lane, wm, wn, As0, As1, Bs0, Bs1, acc);

    #pragma unroll
    for (int mt = 0; mt < 2; mt++) {
        int r = m0 + wm + mt * 16 + (lane >> 2);
        #pragma unroll
        for (int nt = 0; nt < 4; nt++) {
            int c = n0 + wn + nt * 8 + 2 * (lane & 3);
            float b0, b1;
            if (bias_mode) { b0 = g_vbias[c]; b1 = g_vbias[c + 1]; }
            else           { b0 = bias0[c] + bias1[c]; b1 = bias0[c + 1] + bias1[c + 1]; }
            g_gates[(size_t)r * G4H + c]           = acc[mt][nt][0] + b0;
            g_gates[(size_t)r * G4H + c + 1]       = acc[mt][nt][1] + b1;
            g_gates[(size_t)(r + 8) * G4H + c]     = acc[mt][nt][2] + b0;
            g_gates[(size_t)(r + 8) * G4H + c + 1] = acc[mt][nt][3] + b1;
        }
    }
}

// ---------------- LSTM activation: g_gates -> (h, c)
__global__ void k_lstm_act(const float* __restrict__ cprev,
                           float* __restrict__ hout, float* __restrict__ cout,
                           float* __restrict__ hout2) {
    int idx = blockIdx.x * blockDim.x + threadIdx.x;
    if (idx >= BH) return;
    int b = idx / HH, j = idx % HH;
    const float* g = g_gates + (size_t)b * G4H;
    float gi = g[j], gf = g[HH + j], gg = g[2 * HH + j], go = g[3 * HH + j];
    float c = sigf(gf) * cprev[idx] + sigf(gi) * tanhf(gg);
    float h = sigf(go) * tanhf(c);
    hout[idx] = h;
    cout[idx] = c;
    if (hout2) hout2[idx] = h;
}

// ---------------- att_h = h1 @ wh.T + bh  ([B,128])
__global__ void k_atth(const float* __restrict__ h1, const float* __restrict__ wh,
                       const float* __restrict__ bh) {
    __shared__ float hs[512];
    int b = blockIdx.x, t = threadIdx.x;   // 128 threads
    for (int i = t; i < 512; i += 128) hs[i] = h1[(size_t)b * 512 + i];
    __syncthreads();
    const float* w = wh + (size_t)t * 512;
    float acc = bh[t];
    #pragma unroll 8
    for (int k = 0; k < 512; k++) acc += hs[k] * w[k];
    g_atth[b * AD + t] = acc;
}

// ================= fused attention scores, tf32 MMA + HW tanh =================
// rows m in [B*L], S[m,a] = clip2d[m,:].wc[a,:]; scores[m]=sum_a tanh(S+bc+atth[b])*wa[a]+ba
// Block: 64 rows x 128 cols (full A), BK=16, 256 threads (8 warps 2x4, warp 32x32).
__global__ __launch_bounds__(256)
void k_att_scores(const float* __restrict__ clip, const float* __restrict__ wc,
                  const float* __restrict__ bc, const float* __restrict__ wa,
                  const float* __restrict__ ba) {
    __shared__ uint32_t As0[64 * 20], As1[64 * 20];
    __shared__ uint32_t Bs0[128 * 20], Bs1[128 * 20];
    __shared__ float red[64 * 17];
    __shared__ float addsh[128], wash[128];

    int tid = threadIdx.x;
    int wid = tid >> 5, lane = tid & 31;
    int m0 = blockIdx.x * 64;           // row within [B*L]
    int bidx = blockIdx.x >> 2;         // batch (4 blocks per batch, L=256)
    int wm = (wid >> 2) * 32;           // 0 or 32
    int wn = (wid & 3) * 32;            // 0,32,64,96

    if (tid < 128) {
        addsh[tid] = bc[tid] + g_atth[bidx * AD + tid];
        wash[tid] = wa[tid];
    }

    // loaders: A rows 0..63 (1 float4/thread), B rows 0..127 (2 float4/thread)
    int lrow = tid >> 2;                // 0..63
    int kc   = (tid & 3) * 4;
    const float* ap  = clip + (size_t)(m0 + lrow) * CD + kc;
    const float* bp0 = wc + (size_t)lrow * CD + kc;
    const float* bp1 = wc + (size_t)(lrow + 64) * CD + kc;
    int sa  = lrow * 20 + kc;
    int sb1 = (lrow + 64) * 20 + kc;

    uint32_t* As = As0; uint32_t* Asn = As1;
    uint32_t* Bs = Bs0; uint32_t* Bsn = Bs1;

    float acc[2][4][4];
    #pragma unroll
    for (int i = 0; i < 2; i++)
        #pragma unroll
        for (int j = 0; j < 4; j++)
            #pragma unroll
            for (int k = 0; k < 4; k++) acc[i][j][k] = 0.0f;

    {
        float4 ra  = *reinterpret_cast<const float4*>(ap);
        float4 rb0 = *reinterpret_cast<const float4*>(bp0);
        float4 rb1 = *reinterpret_cast<const float4*>(bp1);
        As[sa]=f2tf(ra.x); As[sa+1]=f2tf(ra.y); As[sa+2]=f2tf(ra.z); As[sa+3]=f2tf(ra.w);
        Bs[sa]=f2tf(rb0.x); Bs[sa+1]=f2tf(rb0.y); Bs[sa+2]=f2tf(rb0.z); Bs[sa+3]=f2tf(rb0.w);
        Bs[sb1]=f2tf(rb1.x); Bs[sb1+1]=f2tf(rb1.y); Bs[sb1+2]=f2tf(rb1.z); Bs[sb1+3]=f2tf(rb1.w);
    }
    __syncthreads();

    for (int s = 0; s < 32; s++) {
        float4 ra, rb0, rb1;
        if (s < 31) {
            int k0 = (s + 1) * 16;
            ra  = *reinterpret_cast<const float4*>(ap + k0);
            rb0 = *reinterpret_cast<const float4*>(bp0 + k0);
            rb1 = *reinterpret_cast<const float4*>(bp1 + k0);
        }
        #pragma unroll
        for (int kk = 0; kk < 16; kk += 8) {
            uint32_t af[2][4], bf[4][2];
            int ar = wm + (lane >> 2);
            int ac = kk + (lane & 3);
            #pragma unroll
            for (int mt = 0; mt < 2; mt++) {
                int r = ar + mt * 16;
                af[mt][0] = As[r * 20 + ac];
                af[mt][1] = As[(r + 8) * 20 + ac];
                af[mt][2] = As[r * 20 + ac + 4];
                af[mt][3] = As[(r + 8) * 20 + ac + 4];
            }
            #pragma unroll
            for (int nt = 0; nt < 4; nt++) {
                int c = wn + nt * 8 + (lane >> 2);
                bf[nt][0] = Bs[c * 20 + ac];
                bf[nt][1] = Bs[c * 20 + ac + 4];
            }
            #pragma unroll
            for (int mt = 0; mt < 2; mt++)
                #pragma unroll
                for (int nt = 0; nt < 4; nt++)
                    mma8(acc[mt][nt], af[mt], bf[nt]);
        }
        if (s < 31) {
            Asn[sa]=f2tf(ra.x); Asn[sa+1]=f2tf(ra.y); Asn[sa+2]=f2tf(ra.z); Asn[sa+3]=f2tf(ra.w);
            Bsn[sa]=f2tf(rb0.x); Bsn[sa+1]=f2tf(rb0.y); Bsn[sa+2]=f2tf(rb0.z); Bsn[sa+3]=f2tf(rb0.w);
            Bsn[sb1]=f2tf(rb1.x); Bsn[sb1+1]=f2tf(rb1.y); Bsn[sb1+2]=f2tf(rb1.z); Bsn[sb1+3]=f2tf(rb1.w);
        }
        __syncthreads();
        uint32_t* t;
        t = As; As = Asn; Asn = t;
        t = Bs; Bs = Bsn; Bsn = t;
    }

    // epilogue: tanh + dot with wa; per-thread partials for 4 rows
    float ps[2][2] = {{0.0f, 0.0f}, {0.0f, 0.0f}};
    #pragma unroll
    for (int mt = 0; mt < 2; mt++) {
        #pragma unroll
        for (int nt = 0; nt < 4; nt++) {
            int c = wn + nt * 8 + 2 * (lane & 3);
            float a0 = addsh[c], a1 = addsh[c + 1];
            float w0 = wash[c], w1 = wash[c + 1];
            float t0 = tanh_ap(acc[mt][nt][0] + a0);
            float t1 = tanh_ap(acc[mt][nt][1] + a1);
            float t2 = tanh_ap(acc[mt][nt][2] + a0);
            float t3 = tanh_ap(acc[mt][nt][3] + a1);
            ps[mt][0] += t0 * w0 + t1 * w1;
            ps[mt][1] += t2 * w0 + t3 * w1;
        }
    }
    int slot = (wid & 3) * 4 + (lane & 3);
    #pragma unroll
    for (int mt = 0; mt < 2; mt++) {
        int r = wm + mt * 16 + (lane >> 2);
        red[r * 17 + slot] = ps[mt][0];
        red[(r + 8) * 17 + slot] = ps[mt][1];
    }
    __syncthreads();
    if (tid < 64) {
        float s = ba[0];
        #pragma unroll
        for (int k = 0; k < 16; k++) s += red[tid * 17 + k];
        g_scores[m0 + tid] = s;
    }
}

// ---------------- masked softmax + renorm (per batch row, L=256)
__global__ void k_softmax(const int* __restrict__ mask) {
    __shared__ float sh[256];
    int b = blockIdx.x, t = threadIdx.x;
    float s = g_scores[b * LL + t];
    sh[t] = s;
    __syncthreads();
    for (int o = 128; o > 0; o >>= 1) {
        if (t < o) sh[t] = fmaxf(sh[t], sh[t + o]);
        __syncthreads();
    }
    float mx = sh[0];
    __syncthreads();
    float p = expf(s - mx);
    float pm = p * (float)mask[b * LL + t];
    sh[t] = pm;
    __syncthreads();
    for (int o = 128; o > 0; o >>= 1) {
        if (t < o) sh[t] += sh[t + o];
        __syncthreads();
    }
    float denom = sh[0];
    g_weight[b * LL + t] = pm / denom;
}

// ---------------- att_res[b,c] = sum_l weight[b,l]*clip[b,l,c] (float4)
__global__ void k_attres(const float* __restrict__ clip) {
    __shared__ float w[256];
    int b = blockIdx.x, t = threadIdx.x;   // 128 threads
    w[t] = g_weight[b * LL + t];
    w[t + 128] = g_weight[b * LL + t + 128];
    __syncthreads();
    const float* cb = clip + (size_t)b * LL * CD;
    float4 a = make_float4(0.0f, 0.0f, 0.0f, 0.0f);
    #pragma unroll 4
    for (int l = 0; l < LL; l++) {
        float wl = w[l];
        float4 v = *reinterpret_cast<const float4*>(cb + (size_t)l * CD + t * 4);
        a.x += wl * v.x; a.y += wl * v.y; a.z += wl * v.z; a.w += wl * v.w;
    }
    *reinterpret_cast<float4*>(&g_attres[b * CD + t * 4]) = a;
}

// ---------------- launch ----------------
extern "C" void kernel_launch(void* const* d_in, const int* in_sizes, int n_in,
                              void* d_out, int out_size) {
    const float* xt      = (const float*)d_in[0];
    const float* video   = (const float*)d_in[1];
    const float* event   = (const float*)d_in[2];
    const float* clip    = (const float*)d_in[3];
    const int*   cmask   = (const int*)d_in[4];
    const float* state_h = (const float*)d_in[5];
    const float* state_c = (const float*)d_in[6];
    const float* w_ih0   = (const float*)d_in[7];
    const float* w_hh0   = (const float*)d_in[8];
    const float* b_ih0   = (const float*)d_in[9];
    const float* b_hh0   = (const float*)d_in[10];
    const float* w_ih1   = (const float*)d_in[11];
    const float* w_hh1   = (const float*)d_in[12];
    const float* b_ih1   = (const float*)d_in[13];
    const float* b_hh1   = (const float*)d_in[14];
    const float* w_ih2   = (const float*)d_in[15];
    const float* w_hh2   = (const float*)d_in[16];
    const float* b_ih2   = (const float*)d_in[17];
    const float* b_hh2   = (const float*)d_in[18];
    const float* wc      = (const float*)d_in[19];
    const float* bc      = (const float*)d_in[20];
    const float* wh      = (const float*)d_in[21];
    const float* bh      = (const float*)d_in[22];
    const float* wa      = (const float*)d_in[23];
    const float* ba      = (const float*)d_in[24];

    float* out = (float*)d_out;
    float* h2o = out;            // h2: [B,H]
    float* nh  = out + BH;       // new_h: 3 x [B,H]
    float* nc  = out + 4 * BH;   // new_c: 3 x [B,H]

    dim3 ggrid(G4H / 64, BB / 64);   // (32, 8)

    k_vbias<<<G4H / 256, 256>>>(video, w_ih0, b_ih0, b_hh0);

    // layer 0
    k_gemm3_tf32<<<ggrid, 128>>>(
        xt, 512,               w_ih0, 1536,
        state_h + 2 * BH, 512, w_ih0 + 1024, 1536,
        state_h, 512,          w_hh0, 512,
        b_ih0, b_hh0, /*a0_mode=*/0, /*bias_mode=*/1);
    k_lstm_act<<<BH / 256, 256>>>(state_c, nh, nc, nullptr);

    // layer 1
    k_gemm3_tf32<<<ggrid, 128>>>(
        event, 512,            w_ih1, 1024,
        nh, 512,               w_ih1 + 512, 1024,
        state_h + BH, 512,     w_hh1, 512,
        b_ih1, b_hh1, 0, 0);
    k_lstm_act<<<BH / 256, 256>>>(state_c + BH, nh + BH, nc + BH, nullptr);

    // attention
    k_atth<<<BB, 128>>>(nh + BH, wh, bh);
    k_att_scores<<<(BB * LL) / 64, 256>>>(clip, wc, bc, wa, ba);
    k_softmax<<<BB, 256>>>(cmask);
    k_attres<<<BB, 128>>>(clip);

    // layer 2
    k_gemm3_tf32<<<ggrid, 128>>>(
        nullptr, 512,          w_ih2, 1024,
        nh + BH, 512,          w_ih2 + 512, 1024,
        state_h + 2 * BH, 512, w_hh2, 512,
        b_ih2, b_hh2, /*a0_mode=*/1, 0);
    k_lstm_act<<<BH / 256, 256>>>(state_c + 2 * BH, nh + 2 * BH, nc + 2 * BH, h2o);
}

// round 6
// speedup vs baseline: 2.4435x; 1.2972x over previous
#include <cuda_runtime.h>
#include <math.h>
#include <stdint.h>

#define BB   512
#define LL   256
#define HH   512
#define AD   128
#define CD   512
#define G4H  2048      // 4*H
#define BH   (BB*HH)   // 262144

// ---------------- device scratch ----------------
__device__ alignas(16) float g_gates[BB * G4H];     // 4 MB
__device__ alignas(16) float g_vbias[G4H];
__device__ alignas(16) float g_atth[BB * AD];
__device__ alignas(16) float g_scores[BB * LL];
__device__ alignas(16) float g_weight[BB * LL];
__device__ alignas(16) float g_attres[BB * CD];

__device__ __forceinline__ float sigf(float x) { return 1.0f / (1.0f + expf(-x)); }

__device__ __forceinline__ float tanh_ap(float x) {
    float y;
    asm("tanh.approx.f32 %0, %1;" : "=f"(y) : "f"(x));
    return y;
}

// D += A*B, m16n8k8 tf32 (raw fp32 bits -> HW truncates mantissa)
__device__ __forceinline__ void mma8(float* c, const uint32_t* a, const uint32_t* b) {
    asm volatile("mma.sync.aligned.m16n8k8.row.col.f32.tf32.tf32.f32 "
        "{%0,%1,%2,%3}, {%4,%5,%6,%7}, {%8,%9}, {%0,%1,%2,%3};"
        : "+f"(c[0]), "+f"(c[1]), "+f"(c[2]), "+f"(c[3])
        : "r"(a[0]), "r"(a[1]), "r"(a[2]), "r"(a[3]), "r"(b[0]), "r"(b[1]));
}

__device__ __forceinline__ uint32_t smaddr(const void* p) {
    return (uint32_t)__cvta_generic_to_shared(p);
}
__device__ __forceinline__ void cp16(uint32_t dst, const void* src) {
    asm volatile("cp.async.cg.shared.global [%0], [%1], 16;" :: "r"(dst), "l"(src));
}
__device__ __forceinline__ void cp_commit() { asm volatile("cp.async.commit_group;"); }
template<int N> __device__ __forceinline__ void cp_wait() {
    asm volatile("cp.async.wait_group %0;" :: "n"(N));
}

// ---------------- layer-0 bias: one warp per n, coalesced
__global__ void k_vbias(const float* __restrict__ video,
                        const float* __restrict__ w_ih0,
                        const float* __restrict__ b_ih0,
                        const float* __restrict__ b_hh0) {
    int warp = (blockIdx.x * blockDim.x + threadIdx.x) >> 5;
    int lane = threadIdx.x & 31;
    if (warp >= G4H) return;
    const float* w = w_ih0 + (size_t)warp * 1536 + 512;
    float acc = 0.0f;
    #pragma unroll
    for (int i = 0; i < 16; i++) {
        int k = i * 32 + lane;
        acc += video[k] * w[k];
    }
    #pragma unroll
    for (int o = 16; o > 0; o >>= 1)
        acc += __shfl_xor_sync(0xffffffff, acc, o);
    if (lane == 0) g_vbias[warp] = acc + b_ih0[warp] + b_hh0[warp];
}

// ================= tf32 tensor-core 3-pair NT GEMM (cp.async 3-stage) =============
// g_gates[512,2048] = sum_p A_p[512,512] @ W_p[2048,512]^T + bias
// Block tile 64x64, BK=16, 128 threads (4 warps 2x2, warp tile 32x32).

__device__ __forceinline__ void gemm_pair64(
    const float* __restrict__ Ap, int lda,
    const float* __restrict__ Wp, int ldw,
    int m0, int n0, int tid, int lane, int wm, int wn,
    uint32_t* As, uint32_t* Bs,     // each 3 stages x 64*20
    float acc[2][4][4])
{
    int lrow = tid >> 2;               // 0..31
    int kc   = (tid & 3) * 4;          // 0,4,8,12
    const float* a0p = Ap + (size_t)(m0 + lrow) * lda + kc;
    const float* a1p = Ap + (size_t)(m0 + lrow + 32) * lda + kc;
    const float* b0p = Wp + (size_t)(n0 + lrow) * ldw + kc;
    const float* b1p = Wp + (size_t)(n0 + lrow + 32) * ldw + kc;
    uint32_t sa0 = smaddr(As + lrow * 20 + kc);
    uint32_t sa1 = smaddr(As + (lrow + 32) * 20 + kc);
    uint32_t sb0 = smaddr(Bs + lrow * 20 + kc);
    uint32_t sb1 = smaddr(Bs + (lrow + 32) * 20 + kc);
    const uint32_t SBY = 64 * 20 * 4;  // stage stride bytes

    #pragma unroll
    for (int st = 0; st < 3; st++) {
        int k0 = st * 16;
        cp16(sa0 + st * SBY, a0p + k0);
        cp16(sa1 + st * SBY, a1p + k0);
        cp16(sb0 + st * SBY, b0p + k0);
        cp16(sb1 + st * SBY, b1p + k0);
        cp_commit();
    }

    int stage = 0;
    for (int s = 0; s < 32; s++) {
        cp_wait<2>();
        __syncthreads();
        const uint32_t* Ab = As + stage * 1280;
        const uint32_t* Bb = Bs + stage * 1280;
        #pragma unroll
        for (int kk = 0; kk < 16; kk += 8) {
            uint32_t af[2][4], bf[4][2];
            int ar = wm + (lane >> 2);
            int ac = kk + (lane & 3);
            #pragma unroll
            for (int mt = 0; mt < 2; mt++) {
                int r = ar + mt * 16;
                af[mt][0] = Ab[r * 20 + ac];
                af[mt][1] = Ab[(r + 8) * 20 + ac];
                af[mt][2] = Ab[r * 20 + ac + 4];
                af[mt][3] = Ab[(r + 8) * 20 + ac + 4];
            }
            #pragma unroll
            for (int nt = 0; nt < 4; nt++) {
                int c = wn + nt * 8 + (lane >> 2);
                bf[nt][0] = Bb[c * 20 + ac];
                bf[nt][1] = Bb[c * 20 + ac + 4];
            }
            #pragma unroll
            for (int mt = 0; mt < 2; mt++)
                #pragma unroll
                for (int nt = 0; nt < 4; nt++)
                    mma8(acc[mt][nt], af[mt], bf[nt]);
        }
        __syncthreads();
        if (s < 29) {
            int k0 = (s + 3) * 16;
            cp16(sa0 + stage * SBY, a0p + k0);
            cp16(sa1 + stage * SBY, a1p + k0);
            cp16(sb0 + stage * SBY, b0p + k0);
            cp16(sb1 + stage * SBY, b1p + k0);
        }
        cp_commit();
        stage++; if (stage == 3) stage = 0;
    }
}

__global__ __launch_bounds__(128)
void k_gemm3_tf32(const float* __restrict__ A0, int lda0, const float* __restrict__ W0, int ldw0,
                  const float* __restrict__ A1, int lda1, const float* __restrict__ W1, int ldw1,
                  const float* __restrict__ A2, int lda2, const float* __restrict__ W2, int ldw2,
                  const float* __restrict__ bias0, const float* __restrict__ bias1,
                  int a0_mode, int bias_mode)
{
    __shared__ uint32_t As[3 * 64 * 20];
    __shared__ uint32_t Bs[3 * 64 * 20];
    int tid = threadIdx.x;
    int wid = tid >> 5, lane = tid & 31;
    int m0 = blockIdx.y * 64, n0 = blockIdx.x * 64;
    int wm = (wid >> 1) * 32, wn = (wid & 1) * 32;

    if (a0_mode) A0 = g_attres;

    float acc[2][4][4];
    #pragma unroll
    for (int i = 0; i < 2; i++)
        #pragma unroll
        for (int j = 0; j < 4; j++)
            #pragma unroll
            for (int k = 0; k < 4; k++) acc[i][j][k] = 0.0f;

    gemm_pair64(A0, lda0, W0, ldw0, m0, n0, tid, lane, wm, wn, As, Bs, acc);
    gemm_pair64(A1, lda1, W1, ldw1, m0, n0, tid, lane, wm, wn, As, Bs, acc);
    gemm_pair64(A2, lda2, W2, ldw2, m0, n0, tid, lane, wm, wn, As, Bs, acc);

    #pragma unroll
    for (int mt = 0; mt < 2; mt++) {
        int r = m0 + wm + mt * 16 + (lane >> 2);
        #pragma unroll
        for (int nt = 0; nt < 4; nt++) {
            int c = n0 + wn + nt * 8 + 2 * (lane & 3);
            float b0, b1;
            if (bias_mode) { b0 = g_vbias[c]; b1 = g_vbias[c + 1]; }
            else           { b0 = bias0[c] + bias1[c]; b1 = bias0[c + 1] + bias1[c + 1]; }
            g_gates[(size_t)r * G4H + c]           = acc[mt][nt][0] + b0;
            g_gates[(size_t)r * G4H + c + 1]       = acc[mt][nt][1] + b1;
            g_gates[(size_t)(r + 8) * G4H + c]     = acc[mt][nt][2] + b0;
            g_gates[(size_t)(r + 8) * G4H + c + 1] = acc[mt][nt][3] + b1;
        }
    }
}

// ---------------- LSTM activation: g_gates -> (h, c)
__global__ void k_lstm_act(const float* __restrict__ cprev,
                           float* __restrict__ hout, float* __restrict__ cout,
                           float* __restrict__ hout2) {
    int idx = blockIdx.x * blockDim.x + threadIdx.x;
    if (idx >= BH) return;
    int b = idx / HH, j = idx % HH;
    const float* g = g_gates + (size_t)b * G4H;
    float gi = g[j], gf = g[HH + j], gg = g[2 * HH + j], go = g[3 * HH + j];
    float c = sigf(gf) * cprev[idx] + sigf(gi) * tanhf(gg);
    float h = sigf(go) * tanhf(c);
    hout[idx] = h;
    cout[idx] = c;
    if (hout2) hout2[idx] = h;
}

// ---------------- att_h = h1 @ wh.T + bh  ([B,128])
__global__ void k_atth(const float* __restrict__ h1, const float* __restrict__ wh,
                       const float* __restrict__ bh) {
    __shared__ float hs[512];
    int b = blockIdx.x, t = threadIdx.x;   // 128 threads
    for (int i = t; i < 512; i += 128) hs[i] = h1[(size_t)b * 512 + i];
    __syncthreads();
    const float* w = wh + (size_t)t * 512;
    float acc = bh[t];
    #pragma unroll 8
    for (int k = 0; k < 512; k++) acc += hs[k] * w[k];
    g_atth[b * AD + t] = acc;
}

// ============ fused attention scores, tf32 MMA (cp.async 2-stage) + HW tanh =========
// Block: 64 rows x 128 cols (full A), BK=16, 256 threads (8 warps 2x4, warp 32x32).
__global__ __launch_bounds__(256)
void k_att_scores(const float* __restrict__ clip, const float* __restrict__ wc,
                  const float* __restrict__ bc, const float* __restrict__ wa,
                  const float* __restrict__ ba) {
    __shared__ uint32_t As[2 * 64 * 20];
    __shared__ uint32_t Bs[2 * 128 * 20];
    __shared__ float red[64 * 17];
    __shared__ float addsh[128], wash[128];

    int tid = threadIdx.x;
    int wid = tid >> 5, lane = tid & 31;
    int m0 = blockIdx.x * 64;           // row within [B*L]
    int bidx = blockIdx.x >> 2;         // batch (4 blocks per batch, L=256)
    int wm = (wid >> 2) * 32;           // 0 or 32
    int wn = (wid & 3) * 32;            // 0,32,64,96

    if (tid < 128) {
        addsh[tid] = bc[tid] + g_atth[bidx * AD + tid];
        wash[tid] = wa[tid];
    }

    int lrow = tid >> 2;                // 0..63
    int kc   = (tid & 3) * 4;
    const float* ap  = clip + (size_t)(m0 + lrow) * CD + kc;
    const float* bp0 = wc + (size_t)lrow * CD + kc;
    const float* bp1 = wc + (size_t)(lrow + 64) * CD + kc;
    uint32_t sa  = smaddr(As + lrow * 20 + kc);
    uint32_t sb0 = smaddr(Bs + lrow * 20 + kc);
    uint32_t sb1 = smaddr(Bs + (lrow + 64) * 20 + kc);
    const uint32_t SA = 64 * 20 * 4, SB = 128 * 20 * 4;

    float acc[2][4][4];
    #pragma unroll
    for (int i = 0; i < 2; i++)
        #pragma unroll
        for (int j = 0; j < 4; j++)
            #pragma unroll
            for (int k = 0; k < 4; k++) acc[i][j][k] = 0.0f;

    #pragma unroll
    for (int st = 0; st < 2; st++) {
        int k0 = st * 16;
        cp16(sa + st * SA, ap + k0);
        cp16(sb0 + st * SB, bp0 + k0);
        cp16(sb1 + st * SB, bp1 + k0);
        cp_commit();
    }

    int stage = 0;
    for (int s = 0; s < 32; s++) {
        cp_wait<1>();
        __syncthreads();
        const uint32_t* Ab = As + stage * 1280;
        const uint32_t* Bb = Bs + stage * 2560;
        #pragma unroll
        for (int kk = 0; kk < 16; kk += 8) {
            uint32_t af[2][4], bf[4][2];
            int ar = wm + (lane >> 2);
            int ac = kk + (lane & 3);
            #pragma unroll
            for (int mt = 0; mt < 2; mt++) {
                int r = ar + mt * 16;
                af[mt][0] = Ab[r * 20 + ac];
                af[mt][1] = Ab[(r + 8) * 20 + ac];
                af[mt][2] = Ab[r * 20 + ac + 4];
                af[mt][3] = Ab[(r + 8) * 20 + ac + 4];
            }
            #pragma unroll
            for (int nt = 0; nt < 4; nt++) {
                int c = wn + nt * 8 + (lane >> 2);
                bf[nt][0] = Bb[c * 20 + ac];
                bf[nt][1] = Bb[c * 20 + ac + 4];
            }
            #pragma unroll
            for (int mt = 0; mt < 2; mt++)
                #pragma unroll
                for (int nt = 0; nt < 4; nt++)
                    mma8(acc[mt][nt], af[mt], bf[nt]);
        }
        __syncthreads();
        if (s < 30) {
            int k0 = (s + 2) * 16;
            cp16(sa + stage * SA, ap + k0);
            cp16(sb0 + stage * SB, bp0 + k0);
            cp16(sb1 + stage * SB, bp1 + k0);
        }
        cp_commit();
        stage ^= 1;
    }

    // epilogue: tanh + dot with wa; per-thread partials
    float ps[2][2] = {{0.0f, 0.0f}, {0.0f, 0.0f}};
    #pragma unroll
    for (int mt = 0; mt < 2; mt++) {
        #pragma unroll
        for (int nt = 0; nt < 4; nt++) {
            int c = wn + nt * 8 + 2 * (lane & 3);
            float a0 = addsh[c], a1 = addsh[c + 1];
            float w0 = wash[c], w1 = wash[c + 1];
            float t0 = tanh_ap(acc[mt][nt][0] + a0);
            float t1 = tanh_ap(acc[mt][nt][1] + a1);
            float t2 = tanh_ap(acc[mt][nt][2] + a0);
            float t3 = tanh_ap(acc[mt][nt][3] + a1);
            ps[mt][0] += t0 * w0 + t1 * w1;
            ps[mt][1] += t2 * w0 + t3 * w1;
        }
    }
    int slot = (wid & 3) * 4 + (lane & 3);
    #pragma unroll
    for (int mt = 0; mt < 2; mt++) {
        int r = wm + mt * 16 + (lane >> 2);
        red[r * 17 + slot] = ps[mt][0];
        red[(r + 8) * 17 + slot] = ps[mt][1];
    }
    __syncthreads();
    if (tid < 64) {
        float s = ba[0];
        #pragma unroll
        for (int k = 0; k < 16; k++) s += red[tid * 17 + k];
        g_scores[m0 + tid] = s;
    }
}

// ---------------- masked softmax + renorm (per batch row, L=256)
__global__ void k_softmax(const int* __restrict__ mask) {
    __shared__ float sh[256];
    int b = blockIdx.x, t = threadIdx.x;
    float s = g_scores[b * LL + t];
    sh[t] = s;
    __syncthreads();
    for (int o = 128; o > 0; o >>= 1) {
        if (t < o) sh[t] = fmaxf(sh[t], sh[t + o]);
        __syncthreads();
    }
    float mx = sh[0];
    __syncthreads();
    float p = expf(s - mx);
    float pm = p * (float)mask[b * LL + t];
    sh[t] = pm;
    __syncthreads();
    for (int o = 128; o > 0; o >>= 1) {
        if (t < o) sh[t] += sh[t + o];
        __syncthreads();
    }
    float denom = sh[0];
    g_weight[b * LL + t] = pm / denom;
}

// ---------------- att_res[b,c] = sum_l weight[b,l]*clip[b,l,c] (float4)
__global__ void k_attres(const float* __restrict__ clip) {
    __shared__ float w[256];
    int b = blockIdx.x, t = threadIdx.x;   // 128 threads
    w[t] = g_weight[b * LL + t];
    w[t + 128] = g_weight[b * LL + t + 128];
    __syncthreads();
    const float* cb = clip + (size_t)b * LL * CD;
    float4 a = make_float4(0.0f, 0.0f, 0.0f, 0.0f);
    #pragma unroll 4
    for (int l = 0; l < LL; l++) {
        float wl = w[l];
        float4 v = *reinterpret_cast<const float4*>(cb + (size_t)l * CD + t * 4);
        a.x += wl * v.x; a.y += wl * v.y; a.z += wl * v.z; a.w += wl * v.w;
    }
    *reinterpret_cast<float4*>(&g_attres[b * CD + t * 4]) = a;
}

// ---------------- launch ----------------
extern "C" void kernel_launch(void* const* d_in, const int* in_sizes, int n_in,
                              void* d_out, int out_size) {
    const float* xt      = (const float*)d_in[0];
    const float* video   = (const float*)d_in[1];
    const float* event   = (const float*)d_in[2];
    const float* clip    = (const float*)d_in[3];
    const int*   cmask   = (const int*)d_in[4];
    const float* state_h = (const float*)d_in[5];
    const float* state_c = (const float*)d_in[6];
    const float* w_ih0   = (const float*)d_in[7];
    const float* w_hh0   = (const float*)d_in[8];
    const float* b_ih0   = (const float*)d_in[9];
    const float* b_hh0   = (const float*)d_in[10];
    const float* w_ih1   = (const float*)d_in[11];
    const float* w_hh1   = (const float*)d_in[12];
    const float* b_ih1   = (const float*)d_in[13];
    const float* b_hh1   = (const float*)d_in[14];
    const float* w_ih2   = (const float*)d_in[15];
    const float* w_hh2   = (const float*)d_in[16];
    const float* b_ih2   = (const float*)d_in[17];
    const float* b_hh2   = (const float*)d_in[18];
    const float* wc      = (const float*)d_in[19];
    const float* bc      = (const float*)d_in[20];
    const float* wh      = (const float*)d_in[21];
    const float* bh      = (const float*)d_in[22];
    const float* wa      = (const float*)d_in[23];
    const float* ba      = (const float*)d_in[24];

    float* out = (float*)d_out;
    float* h2o = out;            // h2: [B,H]
    float* nh  = out + BH;       // new_h: 3 x [B,H]
    float* nc  = out + 4 * BH;   // new_c: 3 x [B,H]

    dim3 ggrid(G4H / 64, BB / 64);   // (32, 8)

    k_vbias<<<(G4H * 32) / 256, 256>>>(video, w_ih0, b_ih0, b_hh0);

    // layer 0
    k_gemm3_tf32<<<ggrid, 128>>>(
        xt, 512,               w_ih0, 1536,
        state_h + 2 * BH, 512, w_ih0 + 1024, 1536,
        state_h, 512,          w_hh0, 512,
        b_ih0, b_hh0, /*a0_mode=*/0, /*bias_mode=*/1);
    k_lstm_act<<<BH / 256, 256>>>(state_c, nh, nc, nullptr);

    // layer 1
    k_gemm3_tf32<<<ggrid, 128>>>(
        event, 512,            w_ih1, 1024,
        nh, 512,               w_ih1 + 512, 1024,
        state_h + BH, 512,     w_hh1, 512,
        b_ih1, b_hh1, 0, 0);
    k_lstm_act<<<BH / 256, 256>>>(state_c + BH, nh + BH, nc + BH, nullptr);

    // attention
    k_atth<<<BB, 128>>>(nh + BH, wh, bh);
    k_att_scores<<<(BB * LL) / 64, 256>>>(clip, wc, bc, wa, ba);
    k_softmax<<<BB, 256>>>(cmask);
    k_attres<<<BB, 128>>>(clip);

    // layer 2
    k_gemm3_tf32<<<ggrid, 128>>>(
        nullptr, 512,          w_ih2, 1024,
        nh + BH, 512,          w_ih2 + 512, 1024,
        state_h + 2 * BH, 512, w_hh2, 512,
        b_ih2, b_hh2, /*a0_mode=*/1, 0);
    k_lstm_act<<<BH / 256, 256>>>(state_c + 2 * BH, nh + 2 * BH, nc + 2 * BH, h2o);
}